// round 14
// baseline (speedup 1.0000x reference)
#include <cuda_runtime.h>
#include <cuda_bf16.h>
#include <cstdint>

#define D        64
#define N_CAP    50048
#define E_CAP    1000448
#define BKT      128           // fixed bucket capacity per dst node
#define NB       96            // nodes per gemm block

// Scratch (static __device__ — no allocations allowed)
__device__ __align__(16) float    g_hW [N_CAP * D];      // fp32 h @ W^T
__device__ __align__(16) unsigned g_hWb[N_CAP * 32];     // bf16x2 hW/den (random gathers)
__device__ float  g_s1 [N_CAP];
__device__ float  g_s2 [N_CAP];
__device__ float  g_den[N_CAP];
__device__ int    g_cur[N_CAP];
__device__ __align__(8) float2 g_bkt[(size_t)N_CAP * BKT];   // (src*16 bits, ex)

// bf16x2 bits -> two fp32 (exact widening, pure ALU)
__device__ __forceinline__ float2 bf2_to_f2(unsigned p) {
    return make_float2(__int_as_float(p << 16),
                       __int_as_float(p & 0xffff0000u));
}

// ---------------------------------------------------------------------------
// Kernel 1: hW = h @ W^T (fp32), s1/s2 via c = W^T a, zero den/cur.
// 96 nodes/block, 256 threads, 6 nodes x 4 feats register tile.
// launch_bounds(256,4): cap 64 regs -> 4 blocks/SM (occ 50% vs 32%).
// kq unroll relaxed to 2 to fit the reg budget without spills.
// ---------------------------------------------------------------------------
__global__ __launch_bounds__(256, 4) void k_gemm(
    const float* __restrict__ h, const float* __restrict__ W,
    const float* __restrict__ a, int N)
{
    __shared__ float4 sh4[NB][17];        // h rows, 16 kq + 1 pad
    __shared__ float4 sA[16][4][16];      // sA[kq][jj][jg] = W[4jg+jj][4kq..+3]
    __shared__ float  sa[2 * D];
    __shared__ float4 sc1[16], sc2[16];   // c = W^T a, as float4 over k

    const int t  = threadIdx.x;
    const int jg = t & 15;
    const int ng = t >> 4;
    const int nbase = blockIdx.x * NB;

    const float4* h4 = reinterpret_cast<const float4*>(h);
    const float4* W4 = reinterpret_cast<const float4*>(W);

    #pragma unroll
    for (int r = 0; r < 6; ++r) {
        int idx  = t + 256 * r;            // 0..1535
        int node = idx >> 4;
        int kq   = idx & 15;
        int gn   = nbase + node;
        sh4[node][kq] = (gn < N) ? h4[gn * 16 + kq]
                                 : make_float4(0.f, 0.f, 0.f, 0.f);
    }
    #pragma unroll
    for (int r = 0; r < 4; ++r) {
        int idx = t + 256 * r;             // 0..1023
        int sjg = idx & 15;
        int sjj = (idx >> 4) & 3;
        int skq = idx >> 6;
        sA[skq][sjj][sjg] = W4[(4 * sjg + sjj) * 16 + skq];
    }
    if (t < 2 * D) sa[t] = a[t];
    __syncthreads();

    // Warps 0-1: c1/c2 from L1-resident global W
    if (t < D) {
        float c1 = 0.f, c2 = 0.f;
        #pragma unroll 16
        for (int j = 0; j < D; ++j) {
            float w = W[j * D + t];
            c1 = fmaf(w, sa[j],     c1);
            c2 = fmaf(w, sa[D + j], c2);
        }
        reinterpret_cast<float*>(sc1)[t] = c1;
        reinterpret_cast<float*>(sc2)[t] = c2;
    }

    float acc[6][4];
    #pragma unroll
    for (int i = 0; i < 6; ++i)
        #pragma unroll
        for (int jj = 0; jj < 4; ++jj) acc[i][jj] = 0.f;

    #pragma unroll 2
    for (int kq = 0; kq < 16; ++kq) {
        float4 w0 = sA[kq][0][jg];
        float4 w1 = sA[kq][1][jg];
        float4 w2 = sA[kq][2][jg];
        float4 w3 = sA[kq][3][jg];
        #pragma unroll
        for (int i = 0; i < 6; ++i) {
            float4 hv = sh4[ng + 16 * i][kq];   // broadcast (2 addrs/warp)
            acc[i][0] = fmaf(hv.x, w0.x, fmaf(hv.y, w0.y, fmaf(hv.z, w0.z, fmaf(hv.w, w0.w, acc[i][0]))));
            acc[i][1] = fmaf(hv.x, w1.x, fmaf(hv.y, w1.y, fmaf(hv.z, w1.z, fmaf(hv.w, w1.w, acc[i][1]))));
            acc[i][2] = fmaf(hv.x, w2.x, fmaf(hv.y, w2.y, fmaf(hv.z, w2.z, fmaf(hv.w, w2.w, acc[i][2]))));
            acc[i][3] = fmaf(hv.x, w3.x, fmaf(hv.y, w3.y, fmaf(hv.z, w3.z, fmaf(hv.w, w3.w, acc[i][3]))));
        }
    }

    float4* hW4 = reinterpret_cast<float4*>(g_hW);
    #pragma unroll
    for (int i = 0; i < 6; ++i) {
        int node = nbase + ng + 16 * i;
        if (node < N)
            hW4[node * 16 + jg] = make_float4(acc[i][0], acc[i][1], acc[i][2], acc[i][3]);
    }
    __syncthreads();   // sc1/sc2 ready

    // s1/s2 tail: one node per thread, float4 dots
    if (t < NB) {
        int node = nbase + t;
        if (node < N) {
            float s1 = 0.f, s2 = 0.f;
            #pragma unroll
            for (int kq = 0; kq < 16; ++kq) {
                float4 v  = sh4[t][kq];
                float4 c1 = sc1[kq], c2 = sc2[kq];
                s1 = fmaf(v.x, c1.x, fmaf(v.y, c1.y, fmaf(v.z, c1.z, fmaf(v.w, c1.w, s1))));
                s2 = fmaf(v.x, c2.x, fmaf(v.y, c2.y, fmaf(v.z, c2.z, fmaf(v.w, c2.w, s2))));
            }
            g_s1[node] = s1;
            g_s2[node] = s2;
            g_den[node] = 0.f;
            g_cur[node] = 0;
        }
    }
}

// ---------------------------------------------------------------------------
// Kernel 2 (single edge pass, 2 edges/thread via int2 loads):
//   ex = exp(leakyrelu(s1[src]+s2[dst]))   (values bounded ~|8|: no max-shift)
//   den[src] += ex;  bucket[dst] gets (src*16, ex)   [pre-scaled for gather]
// ---------------------------------------------------------------------------
__device__ __forceinline__ void edge_one(int s, int d)
{
    float v = g_s1[s] + g_s2[d];
    v = (v > 0.f) ? v : 0.2f * v;
    float ex = __expf(v);
    atomicAdd(&g_den[s], ex);
    int pos = atomicAdd(&g_cur[d], 1);
    if (pos < BKT)                     // safety guard (P(overflow) ~ 0)
        g_bkt[(size_t)d * BKT + pos] = make_float2(__int_as_float(s << 4), ex);
}

__global__ __launch_bounds__(256) void k_edge(const int* __restrict__ ei, int E)
{
    int e0 = (blockIdx.x * 256 + threadIdx.x) * 2;
    if (e0 >= E) return;
    int2 ss = *reinterpret_cast<const int2*>(ei + e0);       // E even -> aligned
    int2 dd = *reinterpret_cast<const int2*>(ei + E + e0);
    edge_one(ss.x, dd.x);
    if (e0 + 1 < E) edge_one(ss.y, dd.y);
}

// ---------------------------------------------------------------------------
// Kernel 3: hWn[s] = hW[s] / den[s], bf16. One thread per (node, float4 chunk).
// ---------------------------------------------------------------------------
__global__ __launch_bounds__(256) void k_norm(int N)
{
    int idx  = blockIdx.x * 256 + threadIdx.x;
    int node = idx >> 4;
    int q    = idx & 15;
    if (node >= N) return;
    float rden = __frcp_rn(g_den[node]);     // broadcast across 16 threads
    float4 v = reinterpret_cast<const float4*>(g_hW)[node * 16 + q];
    __nv_bfloat162 b0 = __floats2bfloat162_rn(v.x * rden, v.y * rden);
    __nv_bfloat162 b1 = __floats2bfloat162_rn(v.z * rden, v.w * rden);
    uint2 packed;
    packed.x = *reinterpret_cast<unsigned*>(&b0);
    packed.y = *reinterpret_cast<unsigned*>(&b1);
    reinterpret_cast<uint2*>(g_hWb)[node * 16 + q] = packed;
}

// ---------------------------------------------------------------------------
// Kernel 4: gather + fused LayerNorm (round-13 form, best measured 24.8us).
// One warp per node, two edges in flight (one per half-warp), uint2 per lane.
// ---------------------------------------------------------------------------
__global__ __launch_bounds__(256) void k_gather_ln(
    const float* __restrict__ gamma, const float* __restrict__ beta,
    float* __restrict__ out, int N)
{
    int node = (blockIdx.x * 256 + threadIdx.x) >> 5;
    int lane = threadIdx.x & 31;
    int half = lane >> 4;
    int hl   = lane & 15;
    if (node >= N) return;

    // acc = features [4hl .. 4hl+3]; half 0 seeded with fp32 self term
    float ax = 0.f, ay = 0.f, az = 0.f, aw = 0.f;
    if (half == 0) {
        float4 s = reinterpret_cast<const float4*>(g_hW)[node * 16 + hl];
        ax = s.x; ay = s.y; az = s.z; aw = s.w;
    }

    int cnt = g_cur[node];
    if (cnt > BKT) cnt = BKT;
    const float2* bkt  = g_bkt + (size_t)node * BKT;
    const uint2*  hwb2 = reinterpret_cast<const uint2*>(g_hWb);

    int base = 0;
    for (; base + 8 <= cnt; base += 8) {
        float2 p0 = bkt[base     + half];
        float2 p1 = bkt[base + 2 + half];
        float2 p2 = bkt[base + 4 + half];
        float2 p3 = bkt[base + 6 + half];
        uint2 q0 = hwb2[__float_as_int(p0.x) + hl];
        uint2 q1 = hwb2[__float_as_int(p1.x) + hl];
        uint2 q2 = hwb2[__float_as_int(p2.x) + hl];
        uint2 q3 = hwb2[__float_as_int(p3.x) + hl];
        {
            float2 lo = bf2_to_f2(q0.x), hi = bf2_to_f2(q0.y);
            ax = fmaf(p0.y, lo.x, ax);  ay = fmaf(p0.y, lo.y, ay);
            az = fmaf(p0.y, hi.x, az);  aw = fmaf(p0.y, hi.y, aw);
        }
        {
            float2 lo = bf2_to_f2(q1.x), hi = bf2_to_f2(q1.y);
            ax = fmaf(p1.y, lo.x, ax);  ay = fmaf(p1.y, lo.y, ay);
            az = fmaf(p1.y, hi.x, az);  aw = fmaf(p1.y, hi.y, aw);
        }
        {
            float2 lo = bf2_to_f2(q2.x), hi = bf2_to_f2(q2.y);
            ax = fmaf(p2.y, lo.x, ax);  ay = fmaf(p2.y, lo.y, ay);
            az = fmaf(p2.y, hi.x, az);  aw = fmaf(p2.y, hi.y, aw);
        }
        {
            float2 lo = bf2_to_f2(q3.x), hi = bf2_to_f2(q3.y);
            ax = fmaf(p3.y, lo.x, ax);  ay = fmaf(p3.y, lo.y, ay);
            az = fmaf(p3.y, hi.x, az);  aw = fmaf(p3.y, hi.y, aw);
        }
    }
    for (int e = base + half; e < cnt; e += 2) {
        float2 p = bkt[e];
        uint2  q = hwb2[__float_as_int(p.x) + hl];
        float2 lo = bf2_to_f2(q.x), hi = bf2_to_f2(q.y);
        ax = fmaf(p.y, lo.x, ax);  ay = fmaf(p.y, lo.y, ay);
        az = fmaf(p.y, hi.x, az);  aw = fmaf(p.y, hi.y, aw);
    }

    // combine the two halves (each lane pair hl / hl+16 holds same features)
    ax += __shfl_xor_sync(0xFFFFFFFFu, ax, 16);
    ay += __shfl_xor_sync(0xFFFFFFFFu, ay, 16);
    az += __shfl_xor_sync(0xFFFFFFFFu, az, 16);
    aw += __shfl_xor_sync(0xFFFFFFFFu, aw, 16);

    // LayerNorm over 64 values (16 lanes x 4 each; both halves redundant)
    float sum = (ax + ay) + (az + aw);
    float ss  = fmaf(ax, ax, fmaf(ay, ay, fmaf(az, az, aw * aw)));
    #pragma unroll
    for (int off = 8; off; off >>= 1) {
        sum += __shfl_xor_sync(0xFFFFFFFFu, sum, off);
        ss  += __shfl_xor_sync(0xFFFFFFFFu, ss,  off);
    }
    float mean = sum * (1.f / 64.f);
    float var  = ss * (1.f / 64.f) - mean * mean;
    float inv  = rsqrtf(var + 1e-5f);

    if (half == 0) {
        float4 gm = reinterpret_cast<const float4*>(gamma)[hl];
        float4 bt = reinterpret_cast<const float4*>(beta)[hl];
        float4 o;
        o.x = (ax - mean) * inv * gm.x + bt.x;
        o.y = (ay - mean) * inv * gm.y + bt.y;
        o.z = (az - mean) * inv * gm.z + bt.z;
        o.w = (aw - mean) * inv * gm.w + bt.w;
        reinterpret_cast<float4*>(out)[node * 16 + hl] = o;
    }
}

// ---------------------------------------------------------------------------
extern "C" void kernel_launch(void* const* d_in, const int* in_sizes, int n_in,
                              void* d_out, int out_size)
{
    const float* h     = (const float*)d_in[0];
    const int*   ei    = (const int*)  d_in[1];
    const float* W     = (const float*)d_in[2];
    const float* a     = (const float*)d_in[3];
    const float* gamma = (const float*)d_in[4];
    const float* beta  = (const float*)d_in[5];
    float*       out   = (float*)d_out;

    const int N = in_sizes[0] / D;
    const int E = in_sizes[1] / 2;

    k_gemm     <<<(N + NB - 1) / NB, 256>>>(h, W, a, N);
    k_edge     <<<(E / 2 + 255) / 256, 256>>>(ei, E);
    k_norm     <<<(N * 16 + 255) / 256, 256>>>(N);
    k_gather_ln<<<(N * 32 + 255) / 256, 256>>>(gamma, beta, out, N);
}

// round 15
// speedup vs baseline: 1.0294x; 1.0294x over previous
#include <cuda_runtime.h>
#include <cuda_bf16.h>
#include <cstdint>

#define D        64
#define N_CAP    50048
#define E_CAP    1000448
#define BKT      128           // fixed bucket capacity per dst node
#define NB       96            // nodes per gemm block

// Scratch (static __device__ — no allocations allowed)
__device__ __align__(16) float    g_hW [N_CAP * D];      // fp32 h @ W^T
__device__ __align__(16) unsigned g_hWb[N_CAP * 32];     // bf16x2 hW/den (random gathers)
__device__ float  g_s1 [N_CAP];
__device__ float  g_s2 [N_CAP];
__device__ float  g_den[N_CAP];
__device__ int    g_cur[N_CAP];
__device__ __align__(8) float2 g_bkt[(size_t)N_CAP * BKT];   // (src*16 bits, ex)

// bf16x2 bits -> two fp32 (exact widening, pure ALU)
__device__ __forceinline__ float2 bf2_to_f2(unsigned p) {
    return make_float2(__int_as_float(p << 16),
                       __int_as_float(p & 0xffff0000u));
}

// packed fp32x2 FMA: acc = a * b + acc (full fp32 precision, 2 lanes/instr)
__device__ __forceinline__ void fma2(unsigned long long& acc,
                                     unsigned long long a,
                                     unsigned long long b) {
    asm("fma.rn.f32x2 %0, %1, %2, %0;" : "+l"(acc) : "l"(a), "l"(b));
}

// ---------------------------------------------------------------------------
// Kernel 1: hW = h @ W^T (fp32), s1/s2 via c = W^T a, zero den/cur.
// 96 nodes/block, 256 threads, 6 nodes x 4 feats register tile.
// Inner loop on fma.rn.f32x2: (even-k, odd-k) partial pairs, native float4
// register pairs -> 48 FFMA2 + 10 LDS per kq (was 96 FFMA + 10 LDS).
// ---------------------------------------------------------------------------
__global__ __launch_bounds__(256) void k_gemm(
    const float* __restrict__ h, const float* __restrict__ W,
    const float* __restrict__ a, int N)
{
    __shared__ float4 sh4[NB][17];        // h rows, 16 kq + 1 pad
    __shared__ float4 sA[16][4][16];      // sA[kq][jj][jg] = W[4jg+jj][4kq..+3]
    __shared__ float  sa[2 * D];
    __shared__ float4 sc1[16], sc2[16];   // c = W^T a, as float4 over k

    const int t  = threadIdx.x;
    const int jg = t & 15;
    const int ng = t >> 4;
    const int nbase = blockIdx.x * NB;

    const float4* h4 = reinterpret_cast<const float4*>(h);
    const float4* W4 = reinterpret_cast<const float4*>(W);

    #pragma unroll
    for (int r = 0; r < 6; ++r) {
        int idx  = t + 256 * r;            // 0..1535
        int node = idx >> 4;
        int kq   = idx & 15;
        int gn   = nbase + node;
        sh4[node][kq] = (gn < N) ? h4[gn * 16 + kq]
                                 : make_float4(0.f, 0.f, 0.f, 0.f);
    }
    #pragma unroll
    for (int r = 0; r < 4; ++r) {
        int idx = t + 256 * r;             // 0..1023
        int sjg = idx & 15;
        int sjj = (idx >> 4) & 3;
        int skq = idx >> 6;
        sA[skq][sjj][sjg] = W4[(4 * sjg + sjj) * 16 + skq];
    }
    if (t < 2 * D) sa[t] = a[t];
    __syncthreads();

    // Warps 0-1: c1/c2 from L1-resident global W
    if (t < D) {
        float c1 = 0.f, c2 = 0.f;
        #pragma unroll 16
        for (int j = 0; j < D; ++j) {
            float w = W[j * D + t];
            c1 = fmaf(w, sa[j],     c1);
            c2 = fmaf(w, sa[D + j], c2);
        }
        reinterpret_cast<float*>(sc1)[t] = c1;
        reinterpret_cast<float*>(sc2)[t] = c2;
    }

    // accP[i][jj] = packed (even-k partial, odd-k partial)
    unsigned long long accP[6][4];
    #pragma unroll
    for (int i = 0; i < 6; ++i)
        #pragma unroll
        for (int jj = 0; jj < 4; ++jj) accP[i][jj] = 0ull;

    #pragma unroll 4
    for (int kq = 0; kq < 16; ++kq) {
        ulonglong2 w0 = *reinterpret_cast<const ulonglong2*>(&sA[kq][0][jg]);
        ulonglong2 w1 = *reinterpret_cast<const ulonglong2*>(&sA[kq][1][jg]);
        ulonglong2 w2 = *reinterpret_cast<const ulonglong2*>(&sA[kq][2][jg]);
        ulonglong2 w3 = *reinterpret_cast<const ulonglong2*>(&sA[kq][3][jg]);
        #pragma unroll
        for (int i = 0; i < 6; ++i) {
            ulonglong2 hv = *reinterpret_cast<const ulonglong2*>(&sh4[ng + 16 * i][kq]);
            fma2(accP[i][0], hv.x, w0.x);  fma2(accP[i][0], hv.y, w0.y);
            fma2(accP[i][1], hv.x, w1.x);  fma2(accP[i][1], hv.y, w1.y);
            fma2(accP[i][2], hv.x, w2.x);  fma2(accP[i][2], hv.y, w2.y);
            fma2(accP[i][3], hv.x, w3.x);  fma2(accP[i][3], hv.y, w3.y);
        }
    }

    float4* hW4 = reinterpret_cast<float4*>(g_hW);
    #pragma unroll
    for (int i = 0; i < 6; ++i) {
        int node = nbase + ng + 16 * i;
        if (node < N) {
            float4 o;
            float2 f0 = *reinterpret_cast<float2*>(&accP[i][0]);
            float2 f1 = *reinterpret_cast<float2*>(&accP[i][1]);
            float2 f2 = *reinterpret_cast<float2*>(&accP[i][2]);
            float2 f3 = *reinterpret_cast<float2*>(&accP[i][3]);
            o.x = f0.x + f0.y;
            o.y = f1.x + f1.y;
            o.z = f2.x + f2.y;
            o.w = f3.x + f3.y;
            hW4[node * 16 + jg] = o;
        }
    }
    __syncthreads();   // sc1/sc2 ready

    // s1/s2 tail: one node per thread, float4 dots
    if (t < NB) {
        int node = nbase + t;
        if (node < N) {
            float s1 = 0.f, s2 = 0.f;
            #pragma unroll
            for (int kq = 0; kq < 16; ++kq) {
                float4 v  = sh4[t][kq];
                float4 c1 = sc1[kq], c2 = sc2[kq];
                s1 = fmaf(v.x, c1.x, fmaf(v.y, c1.y, fmaf(v.z, c1.z, fmaf(v.w, c1.w, s1))));
                s2 = fmaf(v.x, c2.x, fmaf(v.y, c2.y, fmaf(v.z, c2.z, fmaf(v.w, c2.w, s2))));
            }
            g_s1[node] = s1;
            g_s2[node] = s2;
            g_den[node] = 0.f;
            g_cur[node] = 0;
        }
    }
}

// ---------------------------------------------------------------------------
// Kernel 2 (single edge pass, 2 edges/thread via int2 loads):
//   ex = exp(leakyrelu(s1[src]+s2[dst]))   (values bounded ~|8|: no max-shift)
//   den[src] += ex;  bucket[dst] gets (src*16, ex)   [pre-scaled for gather]
// ---------------------------------------------------------------------------
__device__ __forceinline__ void edge_one(int s, int d)
{
    float v = g_s1[s] + g_s2[d];
    v = (v > 0.f) ? v : 0.2f * v;
    float ex = __expf(v);
    atomicAdd(&g_den[s], ex);
    int pos = atomicAdd(&g_cur[d], 1);
    if (pos < BKT)                     // safety guard (P(overflow) ~ 0)
        g_bkt[(size_t)d * BKT + pos] = make_float2(__int_as_float(s << 4), ex);
}

__global__ __launch_bounds__(256) void k_edge(const int* __restrict__ ei, int E)
{
    int e0 = (blockIdx.x * 256 + threadIdx.x) * 2;
    if (e0 >= E) return;
    int2 ss = *reinterpret_cast<const int2*>(ei + e0);       // E even -> aligned
    int2 dd = *reinterpret_cast<const int2*>(ei + E + e0);
    edge_one(ss.x, dd.x);
    if (e0 + 1 < E) edge_one(ss.y, dd.y);
}

// ---------------------------------------------------------------------------
// Kernel 3: hWn[s] = hW[s] / den[s], bf16. One thread per (node, float4 chunk).
// ---------------------------------------------------------------------------
__global__ __launch_bounds__(256) void k_norm(int N)
{
    int idx  = blockIdx.x * 256 + threadIdx.x;
    int node = idx >> 4;
    int q    = idx & 15;
    if (node >= N) return;
    float rden = __frcp_rn(g_den[node]);     // broadcast across 16 threads
    float4 v = reinterpret_cast<const float4*>(g_hW)[node * 16 + q];
    __nv_bfloat162 b0 = __floats2bfloat162_rn(v.x * rden, v.y * rden);
    __nv_bfloat162 b1 = __floats2bfloat162_rn(v.z * rden, v.w * rden);
    uint2 packed;
    packed.x = *reinterpret_cast<unsigned*>(&b0);
    packed.y = *reinterpret_cast<unsigned*>(&b1);
    reinterpret_cast<uint2*>(g_hWb)[node * 16 + q] = packed;
}

// ---------------------------------------------------------------------------
// Kernel 4: gather + fused LayerNorm (round-13 form, best measured 24.8us).
// One warp per node, two edges in flight (one per half-warp), uint2 per lane.
// ---------------------------------------------------------------------------
__global__ __launch_bounds__(256) void k_gather_ln(
    const float* __restrict__ gamma, const float* __restrict__ beta,
    float* __restrict__ out, int N)
{
    int node = (blockIdx.x * 256 + threadIdx.x) >> 5;
    int lane = threadIdx.x & 31;
    int half = lane >> 4;
    int hl   = lane & 15;
    if (node >= N) return;

    // acc = features [4hl .. 4hl+3]; half 0 seeded with fp32 self term
    float ax = 0.f, ay = 0.f, az = 0.f, aw = 0.f;
    if (half == 0) {
        float4 s = reinterpret_cast<const float4*>(g_hW)[node * 16 + hl];
        ax = s.x; ay = s.y; az = s.z; aw = s.w;
    }

    int cnt = g_cur[node];
    if (cnt > BKT) cnt = BKT;
    const float2* bkt  = g_bkt + (size_t)node * BKT;
    const uint2*  hwb2 = reinterpret_cast<const uint2*>(g_hWb);

    int base = 0;
    for (; base + 8 <= cnt; base += 8) {
        float2 p0 = bkt[base     + half];
        float2 p1 = bkt[base + 2 + half];
        float2 p2 = bkt[base + 4 + half];
        float2 p3 = bkt[base + 6 + half];
        uint2 q0 = hwb2[__float_as_int(p0.x) + hl];
        uint2 q1 = hwb2[__float_as_int(p1.x) + hl];
        uint2 q2 = hwb2[__float_as_int(p2.x) + hl];
        uint2 q3 = hwb2[__float_as_int(p3.x) + hl];
        {
            float2 lo = bf2_to_f2(q0.x), hi = bf2_to_f2(q0.y);
            ax = fmaf(p0.y, lo.x, ax);  ay = fmaf(p0.y, lo.y, ay);
            az = fmaf(p0.y, hi.x, az);  aw = fmaf(p0.y, hi.y, aw);
        }
        {
            float2 lo = bf2_to_f2(q1.x), hi = bf2_to_f2(q1.y);
            ax = fmaf(p1.y, lo.x, ax);  ay = fmaf(p1.y, lo.y, ay);
            az = fmaf(p1.y, hi.x, az);  aw = fmaf(p1.y, hi.y, aw);
        }
        {
            float2 lo = bf2_to_f2(q2.x), hi = bf2_to_f2(q2.y);
            ax = fmaf(p2.y, lo.x, ax);  ay = fmaf(p2.y, lo.y, ay);
            az = fmaf(p2.y, hi.x, az);  aw = fmaf(p2.y, hi.y, aw);
        }
        {
            float2 lo = bf2_to_f2(q3.x), hi = bf2_to_f2(q3.y);
            ax = fmaf(p3.y, lo.x, ax);  ay = fmaf(p3.y, lo.y, ay);
            az = fmaf(p3.y, hi.x, az);  aw = fmaf(p3.y, hi.y, aw);
        }
    }
    for (int e = base + half; e < cnt; e += 2) {
        float2 p = bkt[e];
        uint2  q = hwb2[__float_as_int(p.x) + hl];
        float2 lo = bf2_to_f2(q.x), hi = bf2_to_f2(q.y);
        ax = fmaf(p.y, lo.x, ax);  ay = fmaf(p.y, lo.y, ay);
        az = fmaf(p.y, hi.x, az);  aw = fmaf(p.y, hi.y, aw);
    }

    // combine the two halves (each lane pair hl / hl+16 holds same features)
    ax += __shfl_xor_sync(0xFFFFFFFFu, ax, 16);
    ay += __shfl_xor_sync(0xFFFFFFFFu, ay, 16);
    az += __shfl_xor_sync(0xFFFFFFFFu, az, 16);
    aw += __shfl_xor_sync(0xFFFFFFFFu, aw, 16);

    // LayerNorm over 64 values (16 lanes x 4 each; both halves redundant)
    float sum = (ax + ay) + (az + aw);
    float ss  = fmaf(ax, ax, fmaf(ay, ay, fmaf(az, az, aw * aw)));
    #pragma unroll
    for (int off = 8; off; off >>= 1) {
        sum += __shfl_xor_sync(0xFFFFFFFFu, sum, off);
        ss  += __shfl_xor_sync(0xFFFFFFFFu, ss,  off);
    }
    float mean = sum * (1.f / 64.f);
    float var  = ss * (1.f / 64.f) - mean * mean;
    float inv  = rsqrtf(var + 1e-5f);

    if (half == 0) {
        float4 gm = reinterpret_cast<const float4*>(gamma)[hl];
        float4 bt = reinterpret_cast<const float4*>(beta)[hl];
        float4 o;
        o.x = (ax - mean) * inv * gm.x + bt.x;
        o.y = (ay - mean) * inv * gm.y + bt.y;
        o.z = (az - mean) * inv * gm.z + bt.z;
        o.w = (aw - mean) * inv * gm.w + bt.w;
        reinterpret_cast<float4*>(out)[node * 16 + hl] = o;
    }
}

// ---------------------------------------------------------------------------
extern "C" void kernel_launch(void* const* d_in, const int* in_sizes, int n_in,
                              void* d_out, int out_size)
{
    const float* h     = (const float*)d_in[0];
    const int*   ei    = (const int*)  d_in[1];
    const float* W     = (const float*)d_in[2];
    const float* a     = (const float*)d_in[3];
    const float* gamma = (const float*)d_in[4];
    const float* beta  = (const float*)d_in[5];
    float*       out   = (float*)d_out;

    const int N = in_sizes[0] / D;
    const int E = in_sizes[1] / 2;

    k_gemm     <<<(N + NB - 1) / NB, 256>>>(h, W, a, N);
    k_edge     <<<(E / 2 + 255) / 256, 256>>>(ei, E);
    k_norm     <<<(N * 16 + 255) / 256, 256>>>(N);
    k_gather_ln<<<(N * 32 + 255) / 256, 256>>>(gamma, beta, out, N);
}

// round 17
// speedup vs baseline: 1.1853x; 1.1515x over previous
#include <cuda_runtime.h>
#include <cuda_bf16.h>
#include <cuda_fp16.h>
#include <cstdint>

#define D        64
#define N_CAP    50048
#define E_CAP    1000448
#define BKT      128           // fixed bucket capacity per dst node

// Scratch (static __device__ — no allocations allowed)
__device__ __align__(16) float    g_hW [N_CAP * D];      // fp32 h @ W^T
__device__ __align__(16) unsigned g_hWb[N_CAP * 32];     // bf16x2 hW/den (random gathers)
__device__ float  g_s1 [N_CAP];
__device__ float  g_s2 [N_CAP];
__device__ float  g_den[N_CAP];
__device__ int    g_cur[N_CAP];
__device__ __align__(8) float2 g_bkt[(size_t)N_CAP * BKT];   // (src*16 bits, ex)

// bf16x2 bits -> two fp32 (exact widening, pure ALU)
__device__ __forceinline__ float2 bf2_to_f2(unsigned p) {
    return make_float2(__int_as_float(p << 16),
                       __int_as_float(p & 0xffff0000u));
}

static __device__ __forceinline__ uint32_t sw128b(uint32_t b) {
    return b ^ ((b >> 3) & 0x70u);
}

// ---------------------------------------------------------------------------
// Kernel 1 (HMMA fp16): hW = h @ W^T, s1 = hW@a1, s2 = hW@a2, zero den/cur.
// 128 rows/block, 8 warps, warp = 16 rows x 64 cols via m16n8k16 mma.sync.
// A: fp16 SW128-swizzled smem + ldmatrix.x4 (conflict-free).
// B (=W): fp16 smem, row stride 72 halves -> b0/b1 LDS.32 conflict-free.
// ---------------------------------------------------------------------------
__global__ __launch_bounds__(256) void k_gemm_mma(
    const float* __restrict__ h, const float* __restrict__ W,
    const float* __restrict__ a, int N)
{
    __shared__ __align__(16) __half sh[128 * 64];   // 16 KB, SW128 layout
    __shared__ __align__(4)  __half sw[64 * 72];    // 9 KB, stride-72 rows
    __shared__ float sa[2 * D];

    const int t    = threadIdx.x;
    const int wid  = t >> 5;
    const int lane = t & 31;
    const int base = blockIdx.x * 128;

    // Stage h tile [128 x 64] fp32 -> fp16, SW128 swizzle (rows = 128 B)
    const float2* h2p = reinterpret_cast<const float2*>(h);
    #pragma unroll
    for (int r = 0; r < 16; ++r) {
        int idx = t + 256 * r;             // 0..4095 half2 slots
        int row = idx >> 5;
        int c   = idx & 31;                // half2 column
        int gr  = base + row;
        float2 v = (gr < N) ? h2p[(size_t)gr * 32 + c] : make_float2(0.f, 0.f);
        __half2 hv = __float22half2_rn(v);
        uint32_t byte = (uint32_t)row * 128 + c * 4;
        *reinterpret_cast<__half2*>(
            reinterpret_cast<char*>(sh) + sw128b(byte)) = hv;
    }
    // Stage W [64 x 64] fp32 -> fp16, row stride 72 halves
    const float2* W2p = reinterpret_cast<const float2*>(W);
    #pragma unroll
    for (int r = 0; r < 8; ++r) {
        int idx = t + 256 * r;             // 0..2047 half2 slots
        int j = idx >> 5;
        int c = idx & 31;
        float2 v = W2p[j * 32 + c];
        reinterpret_cast<__half2*>(sw + j * 72)[c] = __float22half2_rn(v);
    }
    if (t < 2 * D) sa[t] = a[t];
    __syncthreads();

    uint32_t sh_u32;
    asm("{.reg .u64 tt; cvta.to.shared.u64 tt, %1; cvt.u32.u64 %0, tt;}"
        : "=r"(sh_u32) : "l"(sh));
    const uint32_t* swu = reinterpret_cast<const uint32_t*>(sw);

    float C[8][4];
    #pragma unroll
    for (int nt = 0; nt < 8; ++nt)
        #pragma unroll
        for (int q = 0; q < 4; ++q) C[nt][q] = 0.f;

    const int rbase = wid * 16;
    const int g  = lane >> 2;
    const int tg = lane & 3;

    #pragma unroll
    for (int ks = 0; ks < 4; ++ks) {
        // ldmatrix.x4: lanes 0-7 rows 0-7 k0 | 8-15 rows 8-15 k0
        //              16-23 rows 0-7 k0+8 | 24-31 rows 8-15 k0+8
        uint32_t byte = (uint32_t)(rbase + (lane & 15)) * 128
                      + (ks * 16 + (lane >> 4) * 8) * 2;
        uint32_t addr = sh_u32 + sw128b(byte);
        uint32_t a0, a1, a2, a3;
        asm volatile("ldmatrix.sync.aligned.m8n8.x4.shared.b16 {%0,%1,%2,%3}, [%4];"
                     : "=r"(a0), "=r"(a1), "=r"(a2), "=r"(a3) : "r"(addr));
        #pragma unroll
        for (int nt = 0; nt < 8; ++nt) {
            // b0 = {W[nt*8+g][ks*16+tg*2], +1}, b1 = same +8 in k
            int w0 = (nt * 8 + g) * 36 + ks * 8 + tg;   // uint32 index
            uint32_t b0 = swu[w0];
            uint32_t b1 = swu[w0 + 4];
            asm volatile(
                "mma.sync.aligned.m16n8k16.row.col.f32.f16.f16.f32 "
                "{%0,%1,%2,%3}, {%4,%5,%6,%7}, {%8,%9}, {%0,%1,%2,%3};"
                : "+f"(C[nt][0]), "+f"(C[nt][1]), "+f"(C[nt][2]), "+f"(C[nt][3])
                : "r"(a0), "r"(a1), "r"(a2), "r"(a3), "r"(b0), "r"(b1));
        }
    }

    // Epilogue: C[nt] = {(g,col),(g,col+1),(g+8,col),(g+8,col+1)}, col=nt*8+tg*2
    int row0 = base + rbase + g;
    int row1 = row0 + 8;
    float s1a = 0.f, s2a = 0.f, s1b = 0.f, s2b = 0.f;
    float2* hW2 = reinterpret_cast<float2*>(g_hW);
    #pragma unroll
    for (int nt = 0; nt < 8; ++nt) {
        int col = nt * 8 + tg * 2;
        if (row0 < N)
            hW2[(size_t)row0 * 32 + (col >> 1)] = make_float2(C[nt][0], C[nt][1]);
        if (row1 < N)
            hW2[(size_t)row1 * 32 + (col >> 1)] = make_float2(C[nt][2], C[nt][3]);
        float g1 = sa[col], g1b = sa[col + 1];
        float g2 = sa[64 + col], g2b = sa[64 + col + 1];
        s1a = fmaf(C[nt][0], g1, fmaf(C[nt][1], g1b, s1a));
        s2a = fmaf(C[nt][0], g2, fmaf(C[nt][1], g2b, s2a));
        s1b = fmaf(C[nt][2], g1, fmaf(C[nt][3], g1b, s1b));
        s2b = fmaf(C[nt][2], g2, fmaf(C[nt][3], g2b, s2b));
    }
    // reduce over the 4-thread tg group (lanes differing in bits 0-1)
    #pragma unroll
    for (int off = 1; off < 4; off <<= 1) {
        s1a += __shfl_xor_sync(0xFFFFFFFFu, s1a, off);
        s2a += __shfl_xor_sync(0xFFFFFFFFu, s2a, off);
        s1b += __shfl_xor_sync(0xFFFFFFFFu, s1b, off);
        s2b += __shfl_xor_sync(0xFFFFFFFFu, s2b, off);
    }
    if (tg == 0) {
        if (row0 < N) {
            g_s1[row0] = s1a;  g_s2[row0] = s2a;
            g_den[row0] = 0.f; g_cur[row0] = 0;
        }
        if (row1 < N) {
            g_s1[row1] = s1b;  g_s2[row1] = s2b;
            g_den[row1] = 0.f; g_cur[row1] = 0;
        }
    }
}

// ---------------------------------------------------------------------------
// Kernel 2 (single edge pass, 2 edges/thread via int2 loads):
//   ex = exp(leakyrelu(s1[src]+s2[dst]))   (values bounded ~|8|: no max-shift)
//   den[src] += ex;  bucket[dst] gets (src*16, ex)   [pre-scaled for gather]
// ---------------------------------------------------------------------------
__device__ __forceinline__ void edge_one(int s, int d)
{
    float v = g_s1[s] + g_s2[d];
    v = (v > 0.f) ? v : 0.2f * v;
    float ex = __expf(v);
    atomicAdd(&g_den[s], ex);
    int pos = atomicAdd(&g_cur[d], 1);
    if (pos < BKT)                     // safety guard (P(overflow) ~ 0)
        g_bkt[(size_t)d * BKT + pos] = make_float2(__int_as_float(s << 4), ex);
}

__global__ __launch_bounds__(256) void k_edge(const int* __restrict__ ei, int E)
{
    int e0 = (blockIdx.x * 256 + threadIdx.x) * 2;
    if (e0 >= E) return;
    int2 ss = *reinterpret_cast<const int2*>(ei + e0);       // E even -> aligned
    int2 dd = *reinterpret_cast<const int2*>(ei + E + e0);
    edge_one(ss.x, dd.x);
    if (e0 + 1 < E) edge_one(ss.y, dd.y);
}

// ---------------------------------------------------------------------------
// Kernel 3: hWn[s] = hW[s] / den[s], bf16. One thread per (node, float4 chunk).
// ---------------------------------------------------------------------------
__global__ __launch_bounds__(256) void k_norm(int N)
{
    int idx  = blockIdx.x * 256 + threadIdx.x;
    int node = idx >> 4;
    int q    = idx & 15;
    if (node >= N) return;
    float rden = __frcp_rn(g_den[node]);     // broadcast across 16 threads
    float4 v = reinterpret_cast<const float4*>(g_hW)[node * 16 + q];
    __nv_bfloat162 b0 = __floats2bfloat162_rn(v.x * rden, v.y * rden);
    __nv_bfloat162 b1 = __floats2bfloat162_rn(v.z * rden, v.w * rden);
    uint2 packed;
    packed.x = *reinterpret_cast<unsigned*>(&b0);
    packed.y = *reinterpret_cast<unsigned*>(&b1);
    reinterpret_cast<uint2*>(g_hWb)[node * 16 + q] = packed;
}

// ---------------------------------------------------------------------------
// Kernel 4: gather + fused LayerNorm (round-13 form, best measured 24.8us).
// One warp per node, two edges in flight (one per half-warp), uint2 per lane.
// ---------------------------------------------------------------------------
__global__ __launch_bounds__(256) void k_gather_ln(
    const float* __restrict__ gamma, const float* __restrict__ beta,
    float* __restrict__ out, int N)
{
    int node = (blockIdx.x * 256 + threadIdx.x) >> 5;
    int lane = threadIdx.x & 31;
    int half = lane >> 4;
    int hl   = lane & 15;
    if (node >= N) return;

    // acc = features [4hl .. 4hl+3]; half 0 seeded with fp32 self term
    float ax = 0.f, ay = 0.f, az = 0.f, aw = 0.f;
    if (half == 0) {
        float4 s = reinterpret_cast<const float4*>(g_hW)[node * 16 + hl];
        ax = s.x; ay = s.y; az = s.z; aw = s.w;
    }

    int cnt = g_cur[node];
    if (cnt > BKT) cnt = BKT;
    const float2* bkt  = g_bkt + (size_t)node * BKT;
    const uint2*  hwb2 = reinterpret_cast<const uint2*>(g_hWb);

    int base = 0;
    for (; base + 8 <= cnt; base += 8) {
        float2 p0 = bkt[base     + half];
        float2 p1 = bkt[base + 2 + half];
        float2 p2 = bkt[base + 4 + half];
        float2 p3 = bkt[base + 6 + half];
        uint2 q0 = hwb2[__float_as_int(p0.x) + hl];
        uint2 q1 = hwb2[__float_as_int(p1.x) + hl];
        uint2 q2 = hwb2[__float_as_int(p2.x) + hl];
        uint2 q3 = hwb2[__float_as_int(p3.x) + hl];
        {
            float2 lo = bf2_to_f2(q0.x), hi = bf2_to_f2(q0.y);
            ax = fmaf(p0.y, lo.x, ax);  ay = fmaf(p0.y, lo.y, ay);
            az = fmaf(p0.y, hi.x, az);  aw = fmaf(p0.y, hi.y, aw);
        }
        {
            float2 lo = bf2_to_f2(q1.x), hi = bf2_to_f2(q1.y);
            ax = fmaf(p1.y, lo.x, ax);  ay = fmaf(p1.y, lo.y, ay);
            az = fmaf(p1.y, hi.x, az);  aw = fmaf(p1.y, hi.y, aw);
        }
        {
            float2 lo = bf2_to_f2(q2.x), hi = bf2_to_f2(q2.y);
            ax = fmaf(p2.y, lo.x, ax);  ay = fmaf(p2.y, lo.y, ay);
            az = fmaf(p2.y, hi.x, az);  aw = fmaf(p2.y, hi.y, aw);
        }
        {
            float2 lo = bf2_to_f2(q3.x), hi = bf2_to_f2(q3.y);
            ax = fmaf(p3.y, lo.x, ax);  ay = fmaf(p3.y, lo.y, ay);
            az = fmaf(p3.y, hi.x, az);  aw = fmaf(p3.y, hi.y, aw);
        }
    }
    for (int e = base + half; e < cnt; e += 2) {
        float2 p = bkt[e];
        uint2  q = hwb2[__float_as_int(p.x) + hl];
        float2 lo = bf2_to_f2(q.x), hi = bf2_to_f2(q.y);
        ax = fmaf(p.y, lo.x, ax);  ay = fmaf(p.y, lo.y, ay);
        az = fmaf(p.y, hi.x, az);  aw = fmaf(p.y, hi.y, aw);
    }

    // combine the two halves (each lane pair hl / hl+16 holds same features)
    ax += __shfl_xor_sync(0xFFFFFFFFu, ax, 16);
    ay += __shfl_xor_sync(0xFFFFFFFFu, ay, 16);
    az += __shfl_xor_sync(0xFFFFFFFFu, az, 16);
    aw += __shfl_xor_sync(0xFFFFFFFFu, aw, 16);

    // LayerNorm over 64 values (16 lanes x 4 each; both halves redundant)
    float sum = (ax + ay) + (az + aw);
    float ss  = fmaf(ax, ax, fmaf(ay, ay, fmaf(az, az, aw * aw)));
    #pragma unroll
    for (int off = 8; off; off >>= 1) {
        sum += __shfl_xor_sync(0xFFFFFFFFu, sum, off);
        ss  += __shfl_xor_sync(0xFFFFFFFFu, ss,  off);
    }
    float mean = sum * (1.f / 64.f);
    float var  = ss * (1.f / 64.f) - mean * mean;
    float inv  = rsqrtf(var + 1e-5f);

    if (half == 0) {
        float4 gm = reinterpret_cast<const float4*>(gamma)[hl];
        float4 bt = reinterpret_cast<const float4*>(beta)[hl];
        float4 o;
        o.x = (ax - mean) * inv * gm.x + bt.x;
        o.y = (ay - mean) * inv * gm.y + bt.y;
        o.z = (az - mean) * inv * gm.z + bt.z;
        o.w = (aw - mean) * inv * gm.w + bt.w;
        reinterpret_cast<float4*>(out)[node * 16 + hl] = o;
    }
}

// ---------------------------------------------------------------------------
extern "C" void kernel_launch(void* const* d_in, const int* in_sizes, int n_in,
                              void* d_out, int out_size)
{
    const float* h     = (const float*)d_in[0];
    const int*   ei    = (const int*)  d_in[1];
    const float* W     = (const float*)d_in[2];
    const float* a     = (const float*)d_in[3];
    const float* gamma = (const float*)d_in[4];
    const float* beta  = (const float*)d_in[5];
    float*       out   = (float*)d_out;

    const int N = in_sizes[0] / D;
    const int E = in_sizes[1] / 2;

    k_gemm_mma <<<(N + 127) / 128, 256>>>(h, W, a, N);
    k_edge     <<<(E / 2 + 255) / 256, 256>>>(ei, E);
    k_norm     <<<(N * 16 + 255) / 256, 256>>>(N);
    k_gather_ln<<<(N * 32 + 255) / 256, 256>>>(gamma, beta, out, N);
}